// round 7
// baseline (speedup 1.0000x reference)
#include <cuda_runtime.h>

#define BATCH 32
#define LSEQ  64
#define HID   256
#define FEAT  512   // 2*DIM_HID per sequence
#define WROW  1024  // 4*DIM_HID, W row length

// Scratch for GEMM outputs (device globals: no allocation)
__device__ float g_y1[BATCH * LSEQ * HID];  // [B, L1, H]
__device__ float g_y2[BATCH * LSEQ * HID];  // [B, L2, H]

// ---------------------------------------------------------------------------
// GEMM: Y[m, h] = sum_k X[m, k] * W[h, k + off]
// M = 2048 (B*L), N = 256 (H), K = 512. NT layout (both K-contiguous).
// Tiles: BM=128, BN=64, BK=16. 256 threads, 8x4 register tile per thread.
// blockIdx.z selects (x1, W[:, :512]) vs (x2, W[:, 512:]).
// ---------------------------------------------------------------------------
__global__ __launch_bounds__(256) void gemm_kernel(
    const float* __restrict__ X1, const float* __restrict__ X2,
    const float* __restrict__ W)
{
    const int zz = blockIdx.z;
    const float* __restrict__ X  = zz ? X2 : X1;
    const float* __restrict__ Wp = W + (zz ? FEAT : 0);
    float* __restrict__ Y = zz ? g_y2 : g_y1;

    __shared__ float As[16][132];  // [k][m], +4 pad: conflict-free STS, 16B-aligned rows
    __shared__ float Bs[16][68];   // [k][n]

    const int tid = threadIdx.x;
    const int m0 = blockIdx.x * 128;
    const int n0 = blockIdx.y * 64;
    const int tx = tid & 15;     // n-dim (16 threads * 4)
    const int ty = tid >> 4;     // m-dim (16 threads * 8)
    const int mReg = ty * 8;
    const int nReg = tx * 4;

    float acc[8][4];
    #pragma unroll
    for (int i = 0; i < 8; ++i)
        #pragma unroll
        for (int j = 0; j < 4; ++j)
            acc[i][j] = 0.0f;

    for (int k0 = 0; k0 < FEAT; k0 += 16) {
        // Load A tile: 128 rows x 16 k = 512 float4, 2 per thread
        #pragma unroll
        for (int p = 0; p < 2; ++p) {
            int lin = tid + p * 256;
            int m   = lin >> 2;
            int k4  = (lin & 3) << 2;
            float4 v = *(const float4*)(X + (size_t)(m0 + m) * FEAT + k0 + k4);
            As[k4 + 0][m] = v.x;
            As[k4 + 1][m] = v.y;
            As[k4 + 2][m] = v.z;
            As[k4 + 3][m] = v.w;
        }
        // Load B tile: 64 n x 16 k = 256 float4, 1 per thread
        {
            int n  = tid >> 2;
            int k4 = (tid & 3) << 2;
            float4 v = *(const float4*)(Wp + (size_t)(n0 + n) * WROW + k0 + k4);
            Bs[k4 + 0][n] = v.x;
            Bs[k4 + 1][n] = v.y;
            Bs[k4 + 2][n] = v.z;
            Bs[k4 + 3][n] = v.w;
        }
        __syncthreads();

        #pragma unroll
        for (int kk = 0; kk < 16; ++kk) {
            float4 a0 = *(const float4*)&As[kk][mReg];
            float4 a1 = *(const float4*)&As[kk][mReg + 4];
            float4 bb = *(const float4*)&Bs[kk][nReg];
            float am[8] = {a0.x, a0.y, a0.z, a0.w, a1.x, a1.y, a1.z, a1.w};
            float bn[4] = {bb.x, bb.y, bb.z, bb.w};
            #pragma unroll
            for (int i = 0; i < 8; ++i)
                #pragma unroll
                for (int j = 0; j < 4; ++j)
                    acc[i][j] += am[i] * bn[j];
        }
        __syncthreads();
    }

    #pragma unroll
    for (int i = 0; i < 8; ++i) {
        float4 v = make_float4(acc[i][0], acc[i][1], acc[i][2], acc[i][3]);
        *(float4*)(Y + (size_t)(m0 + mReg + i) * HID + n0 + nReg) = v;
    }
}

// ---------------------------------------------------------------------------
// Pairwise relu-sum epilogue.
// grid = (B=32, H/64=4), 256 threads. Each block handles one batch and a
// 64-channel slice. Thread = (h in [0,64), iq in [0,4)); iq strides over i.
// out[b,h] = ( sum_{i<sl1,j<sl2} relu(y1[i,h]+y2[j,h]+b[h])
//              + (4096 - sl1*sl2)*relu(b[h]) ) / (sl1*sl2)
// ---------------------------------------------------------------------------
__global__ __launch_bounds__(256) void pair_kernel(
    const int* __restrict__ seq1, const int* __restrict__ seq2,
    const float* __restrict__ bias, float* __restrict__ out)
{
    __shared__ float s1[LSEQ][64];
    __shared__ float s2[LSEQ][64];
    __shared__ float red[4][64];

    const int tid = threadIdx.x;
    const int bi  = blockIdx.x;
    const int hc  = blockIdx.y * 64;

    const int sl1v = seq1[bi];
    const int sl2v = seq2[bi];

    // Stage y1/y2 h-slices: 64 rows x 64 cols = 1024 float4 each, 4/thread
    #pragma unroll
    for (int p = 0; p < 4; ++p) {
        int lin = tid + p * 256;
        int row = lin >> 4;
        int c   = (lin & 15) << 2;
        size_t gofs = ((size_t)bi * LSEQ + row) * HID + hc + c;
        *(float4*)&s1[row][c] = *(const float4*)(g_y1 + gofs);
        *(float4*)&s2[row][c] = *(const float4*)(g_y2 + gofs);
    }
    __syncthreads();

    const int h  = tid & 63;
    const int iq = tid >> 6;
    const float bh = bias[hc + h];

    // 4 independent accumulators to break the FADD dependency chain
    float acc0 = 0.f, acc1 = 0.f, acc2 = 0.f, acc3 = 0.f;
    for (int i = iq; i < sl1v; i += 4) {
        float a = s1[i][h] + bh;
        int j = 0;
        for (; j + 4 <= sl2v; j += 4) {
            acc0 += fmaxf(a + s2[j + 0][h], 0.f);
            acc1 += fmaxf(a + s2[j + 1][h], 0.f);
            acc2 += fmaxf(a + s2[j + 2][h], 0.f);
            acc3 += fmaxf(a + s2[j + 3][h], 0.f);
        }
        for (; j < sl2v; ++j)
            acc0 += fmaxf(a + s2[j][h], 0.f);
    }
    red[iq][h] = (acc0 + acc1) + (acc2 + acc3);
    __syncthreads();

    if (iq == 0) {
        float tot = (red[0][h] + red[1][h]) + (red[2][h] + red[3][h]);
        float np  = (float)(sl1v * sl2v);
        float pad = ((float)(LSEQ * LSEQ) - np) * fmaxf(bh, 0.f);
        out[bi * HID + hc + h] = (tot + pad) / np;
    }
}

// ---------------------------------------------------------------------------
// Inputs (metadata order): x1 [32,64,512] f32, seq_lens1 [32] i32,
//                          x2 [32,64,512] f32, seq_lens2 [32] i32,
//                          W  [256,1024] f32,  b [256] f32
// Output: [32, 256] f32
// ---------------------------------------------------------------------------
extern "C" void kernel_launch(void* const* d_in, const int* in_sizes, int n_in,
                              void* d_out, int out_size) {
    const float* x1  = (const float*)d_in[0];
    const int*   sl1 = (const int*)  d_in[1];
    const float* x2  = (const float*)d_in[2];
    const int*   sl2 = (const int*)  d_in[3];
    const float* W   = (const float*)d_in[4];
    const float* b   = (const float*)d_in[5];
    float* out = (float*)d_out;

    dim3 gGemm(16, 4, 2);   // M/128, N/64, {x1,x2}
    gemm_kernel<<<gGemm, 256>>>(x1, x2, W);

    dim3 gPair(BATCH, 4);   // batch, H/64
    pair_kernel<<<gPair, 256>>>(sl1, sl2, b, out);
}

// round 11
// speedup vs baseline: 1.3757x; 1.3757x over previous
#include <cuda_runtime.h>
#include <cuda_bf16.h>
#include <cstdint>

#define BATCH 32
#define LSEQ  64
#define HID   256
#define FEAT  512
#define WROW  1024
#define MROWS 2048            // B*LSEQ rows per side
#define KTOT  512

// ---------------- device scratch (no allocation) ----------------
__device__ float g_y1[MROWS * HID];
__device__ float g_y2[MROWS * HID];
__device__ __nv_bfloat16 g_xh[2][MROWS * KTOT];
__device__ __nv_bfloat16 g_xl[2][MROWS * KTOT];
__device__ __nv_bfloat16 g_wh[2][HID * KTOT];
__device__ __nv_bfloat16 g_wl[2][HID * KTOT];

// ---------------------------------------------------------------------------
// Convert x1/x2 fp32 -> bf16 hi/lo pairs. grid (1024, 2), 256 thr.
// ---------------------------------------------------------------------------
__global__ __launch_bounds__(256) void convert_x(const float* __restrict__ x1,
                                                 const float* __restrict__ x2) {
    const int z = blockIdx.y;
    const float* src = z ? x2 : x1;
    int i = blockIdx.x * 256 + threadIdx.x;     // float4 index, 262144 total
    float4 v = ((const float4*)src)[i];

    __nv_bfloat162 h01 = __floats2bfloat162_rn(v.x, v.y);
    __nv_bfloat162 h23 = __floats2bfloat162_rn(v.z, v.w);
    float lx = v.x - __bfloat162float(__low2bfloat16(h01));
    float ly = v.y - __bfloat162float(__high2bfloat16(h01));
    float lz = v.z - __bfloat162float(__low2bfloat16(h23));
    float lw = v.w - __bfloat162float(__high2bfloat16(h23));
    __nv_bfloat162 l01 = __floats2bfloat162_rn(lx, ly);
    __nv_bfloat162 l23 = __floats2bfloat162_rn(lz, lw);

    __nv_bfloat162 hp[2] = {h01, h23};
    __nv_bfloat162 lp[2] = {l01, l23};
    *(uint2*)(&g_xh[z][(size_t)i * 4]) = *(const uint2*)hp;
    *(uint2*)(&g_xl[z][(size_t)i * 4]) = *(const uint2*)lp;
}

// ---------------------------------------------------------------------------
// Convert W fp32 [256,1024] -> per-half bf16 hi/lo [2][256,512]. grid 256, 256 thr.
// ---------------------------------------------------------------------------
__global__ __launch_bounds__(256) void convert_w(const float* __restrict__ W) {
    int i = blockIdx.x * 256 + threadIdx.x;     // float4 index, 65536 total
    int n = i >> 8;
    int c4 = (i & 255) * 4;
    int z = c4 >> 9;
    int k = c4 & 511;
    float4 v = *(const float4*)(W + (size_t)n * WROW + c4);

    __nv_bfloat162 h01 = __floats2bfloat162_rn(v.x, v.y);
    __nv_bfloat162 h23 = __floats2bfloat162_rn(v.z, v.w);
    float lx = v.x - __bfloat162float(__low2bfloat16(h01));
    float ly = v.y - __bfloat162float(__high2bfloat16(h01));
    float lz = v.z - __bfloat162float(__low2bfloat16(h23));
    float lw = v.w - __bfloat162float(__high2bfloat16(h23));
    __nv_bfloat162 l01 = __floats2bfloat162_rn(lx, ly);
    __nv_bfloat162 l23 = __floats2bfloat162_rn(lz, lw);

    __nv_bfloat162 hp[2] = {h01, h23};
    __nv_bfloat162 lp[2] = {l01, l23};
    size_t dofs = (size_t)n * KTOT + k;
    *(uint2*)(&g_wh[z][dofs]) = *(const uint2*)hp;
    *(uint2*)(&g_wl[z][dofs]) = *(const uint2*)lp;
}

// ---------------------------------------------------------------------------
// bf16 GEMM via mma.sync.m16n8k16 (plain-sm_103-safe; no tcgen05).
// Y[m,h] = sum over 3 parts: Xh*Wh + Xh*Wl + Xl*Wh   (virtual K = 1536)
// BM=64, BN=128, BK=32; 256 thr = 8 warps (2m x 4n), warp tile 32x32.
// 3-stage cp.async pipeline. SMEM chunks (16B) swizzled: c ^= (row>>1)&3.
// ---------------------------------------------------------------------------
#define STAGE_BYTES 12288     // A 64*64B + B 128*64B
#define NITER 48              // 3 parts * 16 BK-steps

__device__ __forceinline__ uint32_t smem_u32(const void* p) {
    uint32_t a;
    asm("{ .reg .u64 t; cvta.to.shared.u64 t, %1; cvt.u32.u64 %0, t; }"
        : "=r"(a) : "l"(p));
    return a;
}
__device__ __forceinline__ void cp16(uint32_t dst, const void* src) {
    asm volatile("cp.async.cg.shared.global [%0], [%1], 16;"
                 :: "r"(dst), "l"(src) : "memory");
}
__device__ __forceinline__ void ldsm4(uint32_t& r0, uint32_t& r1,
                                      uint32_t& r2, uint32_t& r3, uint32_t addr) {
    asm volatile("ldmatrix.sync.aligned.m8n8.x4.shared.b16 {%0,%1,%2,%3}, [%4];"
                 : "=r"(r0), "=r"(r1), "=r"(r2), "=r"(r3) : "r"(addr));
}
__device__ __forceinline__ void mma16816(float* c, const uint32_t* a,
                                         uint32_t b0, uint32_t b1) {
    asm volatile(
        "mma.sync.aligned.m16n8k16.row.col.f32.bf16.bf16.f32 "
        "{%0,%1,%2,%3}, {%4,%5,%6,%7}, {%8,%9}, {%0,%1,%2,%3};"
        : "+f"(c[0]), "+f"(c[1]), "+f"(c[2]), "+f"(c[3])
        : "r"(a[0]), "r"(a[1]), "r"(a[2]), "r"(a[3]), "r"(b0), "r"(b1));
}

__device__ __forceinline__ void issue_stage(uint32_t sbase, int s, int it,
                                            int z, int m0, int n0, int tid) {
    const int part = it >> 4;
    const int kp = (it & 15) << 5;
    const __nv_bfloat16* __restrict__ A = (part < 2) ? g_xh[z] : g_xl[z];
    const __nv_bfloat16* __restrict__ B = (part == 1) ? g_wl[z] : g_wh[z];
    uint32_t sA = sbase + s * STAGE_BYTES;
    uint32_t sB = sA + 4096;

    // A tile: 64 rows x 4 chunks(16B) = 256, one per thread
    int am = tid >> 2, ac = tid & 3;
    cp16(sA + am * 64 + ((ac ^ ((am >> 1) & 3)) << 4),
         A + (size_t)(m0 + am) * KTOT + kp + ac * 8);
    // B tile: 128 rows x 4 chunks = 512, two per thread
    int bn = tid >> 2, bc = tid & 3;
    cp16(sB + bn * 64 + ((bc ^ ((bn >> 1) & 3)) << 4),
         B + (size_t)(n0 + bn) * KTOT + kp + bc * 8);
    int bn2 = bn + 64;
    cp16(sB + bn2 * 64 + ((bc ^ ((bn2 >> 1) & 3)) << 4),
         B + (size_t)(n0 + bn2) * KTOT + kp + bc * 8);
    asm volatile("cp.async.commit_group;" ::: "memory");
}

__global__ __launch_bounds__(256) void gemm_mma() {
    __shared__ __align__(128) char sm[3 * STAGE_BYTES];
    const uint32_t sbase = smem_u32(sm);
    const int tid = threadIdx.x, lane = tid & 31, wid = tid >> 5;
    const int m0 = blockIdx.x * 64, n0 = blockIdx.y * 128, z = blockIdx.z;
    const int wm = wid >> 2, wn = wid & 3;     // warp grid 2m x 4n

    float acc[2][4][4];                        // [m16 frag][n8 frag][4]
    #pragma unroll
    for (int f = 0; f < 2; ++f)
        #pragma unroll
        for (int g = 0; g < 4; ++g)
            #pragma unroll
            for (int q = 0; q < 4; ++q) acc[f][g][q] = 0.f;

    issue_stage(sbase, 0, 0, z, m0, n0, tid);
    issue_stage(sbase, 1, 1, z, m0, n0, tid);

    for (int it = 0; it < NITER; ++it) {
        const int s = it % 3;
        asm volatile("cp.async.wait_group 1;" ::: "memory");
        __syncthreads();
        const uint32_t sA = sbase + s * STAGE_BYTES;
        const uint32_t sB = sA + 4096;

        #pragma unroll
        for (int kk = 0; kk < 2; ++kk) {       // two k16 steps in BK=32
            uint32_t a[2][4];
            #pragma unroll
            for (int f = 0; f < 2; ++f) {
                int row = wm * 32 + f * 16 + (lane & 15);
                int ch  = kk * 2 + (lane >> 4);
                ldsm4(a[f][0], a[f][1], a[f][2], a[f][3],
                      sA + row * 64 + ((ch ^ ((row >> 1) & 3)) << 4));
            }
            #pragma unroll
            for (int g2 = 0; g2 < 2; ++g2) {   // each x4 yields two n8 frags
                int row = wn * 32 + g2 * 16 + ((lane >> 4) & 1) * 8 + (lane & 7);
                int ch  = kk * 2 + ((lane >> 3) & 1);
                uint32_t b0, b1, b2, b3;
                ldsm4(b0, b1, b2, b3,
                      sB + row * 64 + ((ch ^ ((row >> 1) & 3)) << 4));
                #pragma unroll
                for (int f = 0; f < 2; ++f) {
                    mma16816(acc[f][2 * g2 + 0], a[f], b0, b1);
                    mma16816(acc[f][2 * g2 + 1], a[f], b2, b3);
                }
            }
        }
        __syncthreads();
        if (it + 2 < NITER)
            issue_stage(sbase, (it + 2) % 3, it + 2, z, m0, n0, tid);
    }

    // Epilogue: acc -> g_y
    float* __restrict__ Y = z ? g_y2 : g_y1;
    #pragma unroll
    for (int f = 0; f < 2; ++f) {
        int mr = m0 + wm * 32 + f * 16 + (lane >> 2);
        #pragma unroll
        for (int g = 0; g < 4; ++g) {
            int nc = n0 + wn * 32 + g * 8 + (lane & 3) * 2;
            *(float2*)(Y + (size_t)mr * HID + nc) =
                make_float2(acc[f][g][0], acc[f][g][1]);
            *(float2*)(Y + (size_t)(mr + 8) * HID + nc) =
                make_float2(acc[f][g][2], acc[f][g][3]);
        }
    }
}

// ---------------------------------------------------------------------------
// Pairwise relu-sum epilogue. grid (B=32, H/64=4), 1024 threads (16-way i split).
// out[b,h] = ( sum_{i<sl1,j<sl2} relu(y1+y2+b) + (4096-sl1*sl2)*relu(b) ) / (sl1*sl2)
// ---------------------------------------------------------------------------
__global__ __launch_bounds__(1024) void pair_kernel(
    const int* __restrict__ seq1, const int* __restrict__ seq2,
    const float* __restrict__ bias, float* __restrict__ out)
{
    __shared__ float s1[LSEQ][64];
    __shared__ float s2[LSEQ][64];
    __shared__ float red[16][64];

    const int tid = threadIdx.x;
    const int bi  = blockIdx.x;
    const int hc  = blockIdx.y * 64;

    const int sl1v = seq1[bi];
    const int sl2v = seq2[bi];

    {
        int row = tid >> 4;
        int c   = (tid & 15) << 2;
        size_t g = ((size_t)bi * LSEQ + row) * HID + hc + c;
        *(float4*)&s1[row][c] = *(const float4*)(g_y1 + g);
        *(float4*)&s2[row][c] = *(const float4*)(g_y2 + g);
    }
    __syncthreads();

    const int h  = tid & 63;
    const int iq = tid >> 6;                 // 0..15
    const float bh = bias[hc + h];

    float acc0 = 0.f, acc1 = 0.f, acc2 = 0.f, acc3 = 0.f;
    for (int i = iq; i < sl1v; i += 16) {
        float a = s1[i][h] + bh;
        int j = 0;
        for (; j + 4 <= sl2v; j += 4) {
            acc0 += fmaxf(a + s2[j + 0][h], 0.f);
            acc1 += fmaxf(a + s2[j + 1][h], 0.f);
            acc2 += fmaxf(a + s2[j + 2][h], 0.f);
            acc3 += fmaxf(a + s2[j + 3][h], 0.f);
        }
        for (; j < sl2v; ++j)
            acc0 += fmaxf(a + s2[j][h], 0.f);
    }
    red[iq][h] = (acc0 + acc1) + (acc2 + acc3);
    __syncthreads();

    if (tid < 64) {
        float tot = 0.f;
        #pragma unroll
        for (int q = 0; q < 16; ++q) tot += red[q][tid];
        float np  = (float)(sl1v * sl2v);
        float pad = ((float)(LSEQ * LSEQ) - np) * fmaxf(bias[hc + tid], 0.f);
        out[bi * HID + hc + tid] = (tot + pad) / np;
    }
}

// ---------------------------------------------------------------------------
// Inputs: x1 [32,64,512] f32, seq_lens1 [32] i32, x2 [32,64,512] f32,
//         seq_lens2 [32] i32, W [256,1024] f32, b [256] f32.  Out: [32,256] f32
// ---------------------------------------------------------------------------
extern "C" void kernel_launch(void* const* d_in, const int* in_sizes, int n_in,
                              void* d_out, int out_size) {
    const float* x1  = (const float*)d_in[0];
    const int*   sl1 = (const int*)  d_in[1];
    const float* x2  = (const float*)d_in[2];
    const int*   sl2 = (const int*)  d_in[3];
    const float* W   = (const float*)d_in[4];
    const float* b   = (const float*)d_in[5];
    float* out = (float*)d_out;

    convert_x<<<dim3(1024, 2), 256>>>(x1, x2);
    convert_w<<<256, 256>>>(W);
    gemm_mma<<<dim3(32, 2, 2), 256>>>();
    pair_kernel<<<dim3(BATCH, 4), 1024>>>(sl1, sl2, b, out);
}

// round 12
// speedup vs baseline: 1.8140x; 1.3186x over previous
#include <cuda_runtime.h>
#include <cuda_bf16.h>
#include <cstdint>

#define BATCH 32
#define LSEQ  64
#define HID   256
#define FEAT  512
#define WROW  1024
#define MROWS 2048            // B*LSEQ rows per side
#define KTOT  512

// ---------------- device scratch (no allocation) ----------------
__device__ float g_y1[MROWS * HID];
__device__ float g_y2[MROWS * HID];
__device__ __nv_bfloat16 g_xh[2][MROWS * KTOT];
__device__ __nv_bfloat16 g_xl[2][MROWS * KTOT];
__device__ __nv_bfloat16 g_wh[2][HID * KTOT];
__device__ __nv_bfloat16 g_wl[2][HID * KTOT];

// ---------------------------------------------------------------------------
// Fused conversion: fp32 -> bf16 hi/lo for x1/x2 (blocks 0..2047) and W
// (blocks 2048..2303). One launch instead of two.
// ---------------------------------------------------------------------------
__device__ __forceinline__ void split_bf16(float4 v, uint2& hp, uint2& lp) {
    __nv_bfloat162 h01 = __floats2bfloat162_rn(v.x, v.y);
    __nv_bfloat162 h23 = __floats2bfloat162_rn(v.z, v.w);
    float lx = v.x - __bfloat162float(__low2bfloat16(h01));
    float ly = v.y - __bfloat162float(__high2bfloat16(h01));
    float lz = v.z - __bfloat162float(__low2bfloat16(h23));
    float lw = v.w - __bfloat162float(__high2bfloat16(h23));
    __nv_bfloat162 l01 = __floats2bfloat162_rn(lx, ly);
    __nv_bfloat162 l23 = __floats2bfloat162_rn(lz, lw);
    __nv_bfloat162 hv[2] = {h01, h23};
    __nv_bfloat162 lv[2] = {l01, l23};
    hp = *(const uint2*)hv;
    lp = *(const uint2*)lv;
}

__global__ __launch_bounds__(256) void convert_fused(
    const float* __restrict__ x1, const float* __restrict__ x2,
    const float* __restrict__ W)
{
    const int bid = blockIdx.x;
    if (bid < 2048) {
        const int z = bid >> 10;
        const float* src = z ? x2 : x1;
        int i = (bid & 1023) * 256 + threadIdx.x;   // float4 idx, 262144 per z
        float4 v = ((const float4*)src)[i];
        uint2 hp, lp;
        split_bf16(v, hp, lp);
        *(uint2*)(&g_xh[z][(size_t)i * 4]) = hp;
        *(uint2*)(&g_xl[z][(size_t)i * 4]) = lp;
    } else {
        int i = (bid - 2048) * 256 + threadIdx.x;   // float4 idx, 65536 total
        int n = i >> 8;
        int c4 = (i & 255) * 4;
        int z = c4 >> 9;
        int k = c4 & 511;
        float4 v = *(const float4*)(W + (size_t)n * WROW + c4);
        uint2 hp, lp;
        split_bf16(v, hp, lp);
        size_t dofs = (size_t)n * KTOT + k;
        *(uint2*)(&g_wh[z][dofs]) = hp;
        *(uint2*)(&g_wl[z][dofs]) = lp;
    }
}

// ---------------------------------------------------------------------------
// bf16 GEMM via mma.sync.m16n8k16 (plain-sm_103-safe).
// Y = Xh*Wh + Xh*Wl + Xl*Wh (virtual K = 1536).
// BM=64, BN=128, BK=64; 256 thr = 8 warps (2m x 4n), warp tile 32x32.
// 3-stage cp.async pipeline, 24 iters, ONE barrier per iter.
// SMEM rows are 128B (8 x 16B chunks), swizzle: ch ^= row & 7.
// ---------------------------------------------------------------------------
#define STAGE_BYTES 24576     // A 64*128B (8KB) + B 128*128B (16KB)
#define NITER 24              // 3 parts * 8 BK-steps
#define GEMM_SMEM (3 * STAGE_BYTES)

__device__ __forceinline__ uint32_t smem_u32(const void* p) {
    uint32_t a;
    asm("{ .reg .u64 t; cvta.to.shared.u64 t, %1; cvt.u32.u64 %0, t; }"
        : "=r"(a) : "l"(p));
    return a;
}
__device__ __forceinline__ void cp16(uint32_t dst, const void* src) {
    asm volatile("cp.async.cg.shared.global [%0], [%1], 16;"
                 :: "r"(dst), "l"(src) : "memory");
}
__device__ __forceinline__ void ldsm4(uint32_t& r0, uint32_t& r1,
                                      uint32_t& r2, uint32_t& r3, uint32_t addr) {
    asm volatile("ldmatrix.sync.aligned.m8n8.x4.shared.b16 {%0,%1,%2,%3}, [%4];"
                 : "=r"(r0), "=r"(r1), "=r"(r2), "=r"(r3) : "r"(addr));
}
__device__ __forceinline__ void mma16816(float* c, const uint32_t* a,
                                         uint32_t b0, uint32_t b1) {
    asm volatile(
        "mma.sync.aligned.m16n8k16.row.col.f32.bf16.bf16.f32 "
        "{%0,%1,%2,%3}, {%4,%5,%6,%7}, {%8,%9}, {%0,%1,%2,%3};"
        : "+f"(c[0]), "+f"(c[1]), "+f"(c[2]), "+f"(c[3])
        : "r"(a[0]), "r"(a[1]), "r"(a[2]), "r"(a[3]), "r"(b0), "r"(b1));
}

__device__ __forceinline__ void issue_stage(uint32_t sbase, int s, int it,
                                            int z, int m0, int n0, int tid) {
    const int part = it >> 3;
    const int kp = (it & 7) << 6;               // K offset within 512
    const __nv_bfloat16* __restrict__ A = (part < 2) ? g_xh[z] : g_xl[z];
    const __nv_bfloat16* __restrict__ B = (part == 1) ? g_wl[z] : g_wh[z];
    uint32_t sA = sbase + s * STAGE_BYTES;
    uint32_t sB = sA + 8192;

    // A tile: 64 rows x 8 chunks(16B) = 512, two per thread
    #pragma unroll
    for (int p = 0; p < 2; ++p) {
        int c = tid + p * 256;
        int row = c >> 3, ch = c & 7;
        cp16(sA + row * 128 + ((ch ^ (row & 7)) << 4),
             A + (size_t)(m0 + row) * KTOT + kp + ch * 8);
    }
    // B tile: 128 rows x 8 chunks = 1024, four per thread
    #pragma unroll
    for (int p = 0; p < 4; ++p) {
        int c = tid + p * 256;
        int row = c >> 3, ch = c & 7;
        cp16(sB + row * 128 + ((ch ^ (row & 7)) << 4),
             B + (size_t)(n0 + row) * KTOT + kp + ch * 8);
    }
    asm volatile("cp.async.commit_group;" ::: "memory");
}

__global__ __launch_bounds__(256) void gemm_mma() {
    extern __shared__ char sm[];
    const uint32_t sbase = smem_u32(sm);
    const int tid = threadIdx.x, lane = tid & 31, wid = tid >> 5;
    const int m0 = blockIdx.x * 64, n0 = blockIdx.y * 128, z = blockIdx.z;
    const int wm = wid >> 2, wn = wid & 3;      // warp grid 2m x 4n

    float acc[2][4][4];
    #pragma unroll
    for (int f = 0; f < 2; ++f)
        #pragma unroll
        for (int g = 0; g < 4; ++g)
            #pragma unroll
            for (int q = 0; q < 4; ++q) acc[f][g][q] = 0.f;

    issue_stage(sbase, 0, 0, z, m0, n0, tid);
    issue_stage(sbase, 1, 1, z, m0, n0, tid);

    for (int it = 0; it < NITER; ++it) {
        const int s = it % 3;
        asm volatile("cp.async.wait_group 1;" ::: "memory");
        __syncthreads();
        const uint32_t sA = sbase + s * STAGE_BYTES;
        const uint32_t sB = sA + 8192;

        #pragma unroll
        for (int kk = 0; kk < 4; ++kk) {        // four k16 steps in BK=64
            uint32_t a[2][4];
            #pragma unroll
            for (int f = 0; f < 2; ++f) {
                int row = wm * 32 + f * 16 + (lane & 15);
                int ch  = kk * 2 + (lane >> 4);
                ldsm4(a[f][0], a[f][1], a[f][2], a[f][3],
                      sA + row * 128 + ((ch ^ (row & 7)) << 4));
            }
            #pragma unroll
            for (int g2 = 0; g2 < 2; ++g2) {
                int row = wn * 32 + g2 * 16 + ((lane >> 4) & 1) * 8 + (lane & 7);
                int ch  = kk * 2 + ((lane >> 3) & 1);
                uint32_t b0, b1, b2, b3;
                ldsm4(b0, b1, b2, b3,
                      sB + row * 128 + ((ch ^ (row & 7)) << 4));
                #pragma unroll
                for (int f = 0; f < 2; ++f) {
                    mma16816(acc[f][2 * g2 + 0], a[f], b0, b1);
                    mma16816(acc[f][2 * g2 + 1], a[f], b2, b3);
                }
            }
        }
        // NOTE: no trailing __syncthreads — next iter's top barrier proves all
        // threads finished reading stage (it+2)%3 (== stage (it-1)%3) already.
        if (it + 2 < NITER)
            issue_stage(sbase, (it + 2) % 3, it + 2, z, m0, n0, tid);
    }

    float* __restrict__ Y = z ? g_y2 : g_y1;
    #pragma unroll
    for (int f = 0; f < 2; ++f) {
        int mr = m0 + wm * 32 + f * 16 + (lane >> 2);
        #pragma unroll
        for (int g = 0; g < 4; ++g) {
            int nc = n0 + wn * 32 + g * 8 + (lane & 3) * 2;
            *(float2*)(Y + (size_t)mr * HID + nc) =
                make_float2(acc[f][g][0], acc[f][g][1]);
            *(float2*)(Y + (size_t)(mr + 8) * HID + nc) =
                make_float2(acc[f][g][2], acc[f][g][3]);
        }
    }
}

// ---------------------------------------------------------------------------
// Pairwise relu-sum, packed f32x2. grid (B=32, H/64=4), 1024 threads.
// Thread = (channel-pair hp 0..31, i-slot iq 0..31). Exact relu via
// 0.5*(t + |t|): t+|t| is exactly 2t or 0, *0.5 exact.
// ---------------------------------------------------------------------------
__device__ __forceinline__ unsigned long long f2x_add(unsigned long long a,
                                                      unsigned long long b) {
    unsigned long long r;
    asm("add.rn.f32x2 %0, %1, %2;" : "=l"(r) : "l"(a), "l"(b));
    return r;
}
__device__ __forceinline__ unsigned long long f2x_fma(unsigned long long a,
                                                      unsigned long long b,
                                                      unsigned long long c) {
    unsigned long long r;
    asm("fma.rn.f32x2 %0, %1, %2, %3;" : "=l"(r) : "l"(a), "l"(b), "l"(c));
    return r;
}
#define ABS2_MASK 0x7FFFFFFF7FFFFFFFULL
#define HALF2_C   0x3F0000003F000000ULL   // {0.5f, 0.5f}

__device__ __forceinline__ unsigned long long relu_acc(
    unsigned long long a2, unsigned long long s, unsigned long long acc) {
    unsigned long long t = f2x_add(a2, s);
    unsigned long long u = t & ABS2_MASK;             // |t| per half
    return f2x_fma(f2x_add(t, u), HALF2_C, acc);      // acc += 0.5*(t+|t|)
}

__global__ __launch_bounds__(1024) void pair_kernel(
    const int* __restrict__ seq1, const int* __restrict__ seq2,
    const float* __restrict__ bias, float* __restrict__ out)
{
    __shared__ float s1[LSEQ][64];
    __shared__ float s2[LSEQ][64];
    __shared__ float red[32][64];

    const int tid = threadIdx.x;
    const int bi  = blockIdx.x;
    const int hc  = blockIdx.y * 64;

    const int sl1v = seq1[bi];
    const int sl2v = seq2[bi];

    {   // stage both 64x64 slices: 1024 float4 each, 1/thread
        int row = tid >> 4;
        int c   = (tid & 15) << 2;
        size_t g = ((size_t)bi * LSEQ + row) * HID + hc + c;
        *(float4*)&s1[row][c] = *(const float4*)(g_y1 + g);
        *(float4*)&s2[row][c] = *(const float4*)(g_y2 + g);
    }
    __syncthreads();

    const int hp = tid & 31;          // channel pair -> ch = 2*hp
    const int iq = tid >> 5;          // 0..31, strides over i
    const int ch = hp * 2;
    const unsigned long long bh2 = *(const unsigned long long*)(bias + hc + ch);

    unsigned long long acc0 = 0, acc1 = 0, acc2 = 0, acc3 = 0;
    for (int i = iq; i < sl1v; i += 32) {
        unsigned long long a2 =
            f2x_add(*(const unsigned long long*)&s1[i][ch], bh2);
        int j = 0;
        for (; j + 4 <= sl2v; j += 4) {
            acc0 = relu_acc(a2, *(const unsigned long long*)&s2[j + 0][ch], acc0);
            acc1 = relu_acc(a2, *(const unsigned long long*)&s2[j + 1][ch], acc1);
            acc2 = relu_acc(a2, *(const unsigned long long*)&s2[j + 2][ch], acc2);
            acc3 = relu_acc(a2, *(const unsigned long long*)&s2[j + 3][ch], acc3);
        }
        for (; j < sl2v; ++j)
            acc0 = relu_acc(a2, *(const unsigned long long*)&s2[j][ch], acc0);
    }
    unsigned long long tot2 = f2x_add(f2x_add(acc0, acc1), f2x_add(acc2, acc3));
    red[iq][ch]     = __uint_as_float((uint32_t)tot2);
    red[iq][ch + 1] = __uint_as_float((uint32_t)(tot2 >> 32));
    __syncthreads();

    if (tid < 64) {
        float tot = 0.f;
        #pragma unroll
        for (int q = 0; q < 32; ++q) tot += red[q][tid];
        float np  = (float)(sl1v * sl2v);
        float pad = ((float)(LSEQ * LSEQ) - np) * fmaxf(bias[hc + tid], 0.f);
        out[bi * HID + hc + tid] = (tot + pad) / np;
    }
}

// ---------------------------------------------------------------------------
// Inputs: x1 [32,64,512] f32, seq_lens1 [32] i32, x2 [32,64,512] f32,
//         seq_lens2 [32] i32, W [256,1024] f32, b [256] f32.  Out: [32,256] f32
// ---------------------------------------------------------------------------
extern "C" void kernel_launch(void* const* d_in, const int* in_sizes, int n_in,
                              void* d_out, int out_size) {
    const float* x1  = (const float*)d_in[0];
    const int*   sl1 = (const int*)  d_in[1];
    const float* x2  = (const float*)d_in[2];
    const int*   sl2 = (const int*)  d_in[3];
    const float* W   = (const float*)d_in[4];
    const float* b   = (const float*)d_in[5];
    float* out = (float*)d_out;

    cudaFuncSetAttribute(gemm_mma, cudaFuncAttributeMaxDynamicSharedMemorySize,
                         GEMM_SMEM);

    convert_fused<<<2304, 256>>>(x1, x2, W);
    gemm_mma<<<dim3(32, 2, 2), 256, GEMM_SMEM>>>();
    pair_kernel<<<dim3(BATCH, 4), 1024>>>(sl1, sl2, b, out);
}